// round 15
// baseline (speedup 1.0000x reference)
#include <cuda_runtime.h>
#include <cstdint>

// Blur_by_Kernel: per-batch 21x21 depthwise correlation, reflect pad 10.
// B=16, C=3, H=W=768, K=21.
// R13 = R11 resubmit (infra failure last round, kernel never measured):
// 8x8 per-thread tile to cut peak live regs (acc 64 + rp 28 ~= 92),
// j-outer/iy-inner steady body with transient shifted pairs -> no ptxas
// pair-copy storm. Kernel taps pre-duplicated (k,k) in smem.

#define SW 148                      // smem patch row stride (floats)
#define PATCH_ROWS 148
#define PATCH (SW * PATCH_ROWS)     // 21904 floats
#define SMEM_KD_BYTES 3536          // 441 ull pairs (3528) padded to 16B
#define SMEM_BYTES (SMEM_KD_BYTES + PATCH * 4)   // 91152 -> 2 CTAs/SM

typedef unsigned long long ull;

__device__ __forceinline__ ull dup2(float v) {
    ull r;
    asm("mov.b64 %0, {%1, %1};" : "=l"(r) : "f"(v));
    return r;
}

// returns pair (hi(a), lo(b)) -- the 1-element-shifted pair
__device__ __forceinline__ ull mid2(ull a, ull b) {
    ull r;
    asm("{\n\t"
        ".reg .b32 al, ah, bl, bh;\n\t"
        "mov.b64 {al, ah}, %1;\n\t"
        "mov.b64 {bl, bh}, %2;\n\t"
        "mov.b64 %0, {ah, bl};\n\t"
        "}"
        : "=l"(r) : "l"(a), "l"(b));
    return r;
}

__device__ __forceinline__ void ffma2(ull& d, ull a, ull b) {
    asm("fma.rn.f32x2 %0, %1, %2, %0;" : "+l"(d) : "l"(a), "l"(b));
}

__device__ __forceinline__ void load_rp(const float* __restrict__ row, ull (&rp)[14]) {
#pragma unroll
    for (int c = 0; c < 7; ++c) {
        ulonglong2 v = *reinterpret_cast<const ulonglong2*>(row + c * 4);
        rp[2 * c]     = v.x;
        rp[2 * c + 1] = v.y;
    }
}

// Steady row: all 8 output rows active. kb7 = skd + (rr-7)*21.
// j outer, iy inner; shifted pairs computed once per odd j, shared by 8 iy.
__device__ __forceinline__ void steady_row(const float* __restrict__ row,
                                           const ull* __restrict__ kb7,
                                           ull (&acc)[8][4])
{
    ull rp[14];
    load_rp(row, rp);

#pragma unroll
    for (int j = 0; j < 21; ++j) {
        const int h = j >> 1;
        ull a0, a1, a2, a3;
        if ((j & 1) == 0) {
            a0 = rp[h];     a1 = rp[h + 1];
            a2 = rp[h + 2]; a3 = rp[h + 3];
        } else {
            a0 = mid2(rp[h],     rp[h + 1]);
            a1 = mid2(rp[h + 1], rp[h + 2]);
            a2 = mid2(rp[h + 2], rp[h + 3]);
            a3 = mid2(rp[h + 3], rp[h + 4]);
        }
#pragma unroll
        for (int iy = 0; iy < 8; ++iy) {
            const ull kb = kb7[(7 - iy) * 21 + j];   // LDS.64 broadcast
            ffma2(acc[iy][0], a0, kb);
            ffma2(acc[iy][1], a1, kb);
            ffma2(acc[iy][2], a2, kb);
            ffma2(acc[iy][3], a3, kb);
        }
    }
}

// Edge row: partial iy coverage, guarded per iy. sp array amortizes mid2.
__device__ __forceinline__ void edge_row(const float* __restrict__ row,
                                         const ull* __restrict__ skd,
                                         ull (&acc)[8][4], int rr)
{
    ull rp[14];
    load_rp(row, rp);
    ull sp[13];
#pragma unroll
    for (int h = 0; h < 13; ++h)
        sp[h] = mid2(rp[h], rp[h + 1]);

#pragma unroll
    for (int iy = 0; iy < 8; ++iy) {
        const int i = rr - iy;          // kernel row
        if (i < 0 || i > 20) continue;
        const ull* kr = skd + i * 21;
#pragma unroll
        for (int j = 0; j < 21; ++j) {
            const ull kb = kr[j];
            const int h = j >> 1;
            if ((j & 1) == 0) {
                ffma2(acc[iy][0], rp[h + 0], kb);
                ffma2(acc[iy][1], rp[h + 1], kb);
                ffma2(acc[iy][2], rp[h + 2], kb);
                ffma2(acc[iy][3], rp[h + 3], kb);
            } else {
                ffma2(acc[iy][0], sp[h + 0], kb);
                ffma2(acc[iy][1], sp[h + 1], kb);
                ffma2(acc[iy][2], sp[h + 2], kb);
                ffma2(acc[iy][3], sp[h + 3], kb);
            }
        }
    }
}

__global__ void __launch_bounds__(256, 2)
blur21_kernel(const float* __restrict__ gin_all,
              const float* __restrict__ gker,
              float* __restrict__ gout_all)
{
    extern __shared__ char smem_raw[];
    ull*   s_kd = reinterpret_cast<ull*>(smem_raw);                   // [441] (k,k)
    float* s_in = reinterpret_cast<float*>(smem_raw + SMEM_KD_BYTES); // [148*148]

    const int tid = threadIdx.x;
    const int bc  = blockIdx.z;           // b*3 + c, 0..47
    const int b   = bc / 3;

    const float* gin = gin_all + (size_t)bc * (768 * 768);
    const float* gk  = gker + b * 441;

    const int x0 = blockIdx.x * 128 - 10;
    const int y0 = blockIdx.y * 128 - 10;

    // ---- fill smem patch, warp per row slice (division-free) ----
    {
        const int warp = tid >> 5;
        const int lane = tid & 31;
        for (int py = warp; py < PATCH_ROWS; py += 8) {
            int gy = y0 + py;
            gy = (gy < 0) ? -gy : gy;
            gy = (gy > 767) ? (1534 - gy) : gy;
            const float* grow = gin + gy * 768;
            float* srow = s_in + py * SW;
#pragma unroll
            for (int px = lane; px < SW; px += 32) {
                int gx = x0 + px;
                gx = (gx < 0) ? -gx : gx;
                gx = (gx > 767) ? (1534 - gx) : gx;
                srow[px] = grow[gx];
            }
        }
    }
    // ---- fill kernel as pre-duplicated (k,k) pairs ----
    for (int idx = tid; idx < 441; idx += 256)
        s_kd[idx] = dup2(gk[idx]);
    __syncthreads();

    // thread -> 8 x-outputs (4 pairs) x 8 y-outputs
    const int lx = tid & 15;    // 0..15 -> x block of 8
    const int ly = tid >> 4;    // 0..15 -> y block of 8
    const int xb = lx * 8;

    ull acc[8][4];
#pragma unroll
    for (int iy = 0; iy < 8; ++iy)
#pragma unroll
        for (int p = 0; p < 4; ++p)
            acc[iy][p] = 0ULL;

    const float* base = s_in + (ly * 8) * SW + xb;

    // prologue rows 0..6 (iy 0..rr)
#pragma unroll 1
    for (int rr = 0; rr < 7; ++rr)
        edge_row(base + rr * SW, s_kd, acc, rr);
    // steady rows 7..20: all 8 output rows active
#pragma unroll 1
    for (int rr = 7; rr < 21; ++rr)
        steady_row(base + rr * SW, s_kd + (rr - 7) * 21, acc);
    // epilogue rows 21..27 (iy rr-20..7)
#pragma unroll 1
    for (int rr = 21; rr < 28; ++rr)
        edge_row(base + rr * SW, s_kd, acc, rr);

    // ---- store 8x8 outputs, 16B vector stores ----
    float* gout = gout_all + (size_t)bc * (768 * 768)
                + (size_t)(blockIdx.y * 128 + ly * 8) * 768
                + blockIdx.x * 128 + xb;
#pragma unroll
    for (int iy = 0; iy < 8; ++iy) {
        ulonglong2* o = reinterpret_cast<ulonglong2*>(gout + iy * 768);
        o[0] = make_ulonglong2(acc[iy][0], acc[iy][1]);
        o[1] = make_ulonglong2(acc[iy][2], acc[iy][3]);
    }
}

extern "C" void kernel_launch(void* const* d_in, const int* in_sizes, int n_in,
                              void* d_out, int out_size)
{
    const float* inp = (const float*)d_in[0];   // (16,3,768,768) f32
    const float* ker = (const float*)d_in[1];   // (16,21,21) f32
    float* out = (float*)d_out;                 // (16,3,768,768) f32

    cudaFuncSetAttribute(blur21_kernel,
                         cudaFuncAttributeMaxDynamicSharedMemorySize,
                         SMEM_BYTES);

    dim3 grid(6, 6, 48);   // 768/128 x-tiles, 768/128 y-tiles, 16*3 images
    blur21_kernel<<<grid, 256, SMEM_BYTES>>>(inp, ker, out);
}

// round 16
// speedup vs baseline: 1.3785x; 1.3785x over previous
#include <cuda_runtime.h>
#include <cstdint>

// Blur_by_Kernel: per-batch 21x21 depthwise correlation, reflect pad 10.
// B=16, C=3, H=W=768, K=21.
// R15: stride-64 output pairing + pre-interleaved smem patch.
// acc pair p = (o[x+p], o[x+64+p]); smem stores IL[v] = (in[v], in[v+64]) as
// aligned 8B pairs, so EVERY tap j uses an aligned pair operand. Inner loop
// has zero shuffle ALU: FFMA2 + broadcast LDS.64 + LDS.128 only.

#define KD_PAIRS 441
#define SMEM_KD_BYTES 3536              // 441*8 = 3528 padded to 16
#define IL_W 84                         // interleaved pairs per row
#define IL_ROWS 148
#define SMEM_BYTES (SMEM_KD_BYTES + IL_ROWS * IL_W * 8)   // 102,992 -> 2 CTA/SM

typedef unsigned long long ull;

__device__ __forceinline__ ull dup2(float v) {
    ull r;
    asm("mov.b64 %0, {%1, %1};" : "=l"(r) : "f"(v));
    return r;
}

__device__ __forceinline__ ull pack2(float lo, float hi) {
    ull r;
    asm("mov.b64 %0, {%1, %2};" : "=l"(r) : "f"(lo), "f"(hi));
    return r;
}

__device__ __forceinline__ void unpack2(ull v, float& lo, float& hi) {
    asm("mov.b64 {%0, %1}, %2;" : "=f"(lo), "=f"(hi) : "l"(v));
}

__device__ __forceinline__ void ffma2(ull& d, ull a, ull b) {
    asm("fma.rn.f32x2 %0, %1, %2, %0;" : "+l"(d) : "l"(a), "l"(b));
}

__device__ __forceinline__ int reflect768(int g) {
    g = (g < 0) ? -g : g;
    return (g > 767) ? (1534 - g) : g;
}

// Load 24 interleaved pairs rp[q] = (in[xb+q], in[xb+64+q]) from smem row.
__device__ __forceinline__ void load_rp(const ull* __restrict__ row, ull (&rp)[24]) {
#pragma unroll
    for (int c = 0; c < 12; ++c) {
        ulonglong2 v = *reinterpret_cast<const ulonglong2*>(row + 2 * c);
        rp[2 * c]     = v.x;
        rp[2 * c + 1] = v.y;
    }
}

// Steady row: all 8 output rows active. kb7 = skd + (rr-7)*21.
__device__ __forceinline__ void steady_row(const ull* __restrict__ row,
                                           const ull* __restrict__ kb7,
                                           ull (&acc)[8][4])
{
    ull rp[24];
    load_rp(row, rp);

#pragma unroll
    for (int j = 0; j < 21; ++j) {
#pragma unroll
        for (int iy = 0; iy < 8; ++iy) {
            const ull kb = kb7[(7 - iy) * 21 + j];   // broadcast LDS.64
            ffma2(acc[iy][0], rp[j + 0], kb);
            ffma2(acc[iy][1], rp[j + 1], kb);
            ffma2(acc[iy][2], rp[j + 2], kb);
            ffma2(acc[iy][3], rp[j + 3], kb);
        }
    }
}

// Edge row: partial iy coverage, guarded per iy.
__device__ __forceinline__ void edge_row(const ull* __restrict__ row,
                                         const ull* __restrict__ skd,
                                         ull (&acc)[8][4], int rr)
{
    ull rp[24];
    load_rp(row, rp);

#pragma unroll
    for (int iy = 0; iy < 8; ++iy) {
        const int i = rr - iy;          // kernel row index
        if (i < 0 || i > 20) continue;
        const ull* kr = skd + i * 21;
#pragma unroll
        for (int j = 0; j < 21; ++j) {
            const ull kb = kr[j];
            ffma2(acc[iy][0], rp[j + 0], kb);
            ffma2(acc[iy][1], rp[j + 1], kb);
            ffma2(acc[iy][2], rp[j + 2], kb);
            ffma2(acc[iy][3], rp[j + 3], kb);
        }
    }
}

__global__ void __launch_bounds__(256, 2)
blur21_kernel(const float* __restrict__ gin_all,
              const float* __restrict__ gker,
              float* __restrict__ gout_all)
{
    extern __shared__ char smem_raw[];
    ull* s_kd = reinterpret_cast<ull*>(smem_raw);                   // [441] (k,k)
    ull* s_il = reinterpret_cast<ull*>(smem_raw + SMEM_KD_BYTES);   // [148][84]

    const int tid = threadIdx.x;
    const int bc  = blockIdx.z;           // b*3 + c
    const int b   = bc / 3;

    const float* gin = gin_all + (size_t)bc * (768 * 768);
    const float* gk  = gker + b * 441;

    const int x0 = blockIdx.x * 128 - 10;
    const int y0 = blockIdx.y * 128 - 10;

    // ---- fill interleaved patch: IL[py][v] = (in[x0+v], in[x0+v+64]) ----
    {
        const int warp = tid >> 5;
        const int lane = tid & 31;
        for (int py = warp; py < IL_ROWS; py += 8) {
            const int gy = reflect768(y0 + py);
            const float* grow = gin + gy * 768;
            ull* srow = s_il + py * IL_W;
#pragma unroll
            for (int v = lane; v < IL_W; v += 32) {
                const int gx0 = reflect768(x0 + v);
                const int gx1 = reflect768(x0 + v + 64);
                srow[v] = pack2(grow[gx0], grow[gx1]);
            }
        }
    }
    // ---- kernel as pre-duplicated (k,k) pairs ----
    for (int idx = tid; idx < KD_PAIRS; idx += 256)
        s_kd[idx] = dup2(gk[idx]);
    __syncthreads();

    // thread -> outputs x in [xb,xb+4) u [xb+64,xb+68), y block of 8
    const int lx = tid & 15;    // 0..15 -> xb = lx*4
    const int ly = tid >> 4;    // 0..15 -> y block of 8
    const int xb = lx * 4;

    ull acc[8][4];
#pragma unroll
    for (int iy = 0; iy < 8; ++iy)
#pragma unroll
        for (int p = 0; p < 4; ++p)
            acc[iy][p] = 0ULL;

    const ull* base = s_il + (ly * 8) * IL_W + xb;

    // prologue rows 0..6
#pragma unroll 1
    for (int rr = 0; rr < 7; ++rr)
        edge_row(base + rr * IL_W, s_kd, acc, rr);
    // steady rows 7..20
#pragma unroll 1
    for (int rr = 7; rr < 21; ++rr)
        steady_row(base + rr * IL_W, s_kd + (rr - 7) * 21, acc);
    // epilogue rows 21..27
#pragma unroll 1
    for (int rr = 21; rr < 28; ++rr)
        edge_row(base + rr * IL_W, s_kd, acc, rr);

    // ---- store: unpack pairs -> two float4 per output row ----
    float* gout = gout_all + (size_t)bc * (768 * 768)
                + (size_t)(blockIdx.y * 128 + ly * 8) * 768
                + blockIdx.x * 128 + xb;
#pragma unroll
    for (int iy = 0; iy < 8; ++iy) {
        float lo0, lo1, lo2, lo3, hi0, hi1, hi2, hi3;
        unpack2(acc[iy][0], lo0, hi0);
        unpack2(acc[iy][1], lo1, hi1);
        unpack2(acc[iy][2], lo2, hi2);
        unpack2(acc[iy][3], lo3, hi3);
        float* o = gout + iy * 768;
        *reinterpret_cast<float4*>(o)      = make_float4(lo0, lo1, lo2, lo3);
        *reinterpret_cast<float4*>(o + 64) = make_float4(hi0, hi1, hi2, hi3);
    }
}

extern "C" void kernel_launch(void* const* d_in, const int* in_sizes, int n_in,
                              void* d_out, int out_size)
{
    const float* inp = (const float*)d_in[0];   // (16,3,768,768) f32
    const float* ker = (const float*)d_in[1];   // (16,21,21) f32
    float* out = (float*)d_out;                 // (16,3,768,768) f32

    cudaFuncSetAttribute(blur21_kernel,
                         cudaFuncAttributeMaxDynamicSharedMemorySize,
                         SMEM_BYTES);

    dim3 grid(6, 6, 48);   // 768/128 x-tiles, 768/128 y-tiles, 16*3 images
    blur21_kernel<<<grid, 256, SMEM_BYTES>>>(inp, ker, out);
}

// round 17
// speedup vs baseline: 1.4943x; 1.0840x over previous
#include <cuda_runtime.h>
#include <cstdint>

// Blur_by_Kernel: per-batch 21x21 depthwise correlation, reflect pad 10.
// B=16, C=3, H=W=768, K=21.
// R16: stride-64 interleaved pairing (R15) + 3 CTAs/SM occupancy:
// 128x64 tile (smem 60KB -> 3 resident), 4iy x 4pair per thread,
// two-phase rp loading to fit the 80-reg/thread budget.

#define KD_PAIRS 441
#define SMEM_KD_BYTES 3536              // 441*8 = 3528 padded to 16
#define IL_W 84                         // interleaved pairs per row
#define IL_ROWS 84                      // 64 tile rows + 20 halo
#define SMEM_BYTES (SMEM_KD_BYTES + IL_ROWS * IL_W * 8)   // 59,984 -> 3 CTA/SM

typedef unsigned long long ull;

__device__ __forceinline__ ull dup2(float v) {
    ull r;
    asm("mov.b64 %0, {%1, %1};" : "=l"(r) : "f"(v));
    return r;
}

__device__ __forceinline__ ull pack2(float lo, float hi) {
    ull r;
    asm("mov.b64 %0, {%1, %2};" : "=l"(r) : "f"(lo), "f"(hi));
    return r;
}

__device__ __forceinline__ void unpack2(ull v, float& lo, float& hi) {
    asm("mov.b64 {%0, %1}, %2;" : "=f"(lo), "=f"(hi) : "l"(v));
}

__device__ __forceinline__ void ffma2(ull& d, ull a, ull b) {
    asm("fma.rn.f32x2 %0, %1, %2, %0;" : "+l"(d) : "l"(a), "l"(b));
}

__device__ __forceinline__ int reflect768(int g) {
    g = (g < 0) ? -g : g;
    return (g > 767) ? (1534 - g) : g;
}

// Steady row: all 4 output rows active. kb3 = skd + (rr-3)*21.
// Two phases keep <= ~17 rp pairs live at once.
__device__ __forceinline__ void steady_row(const ull* __restrict__ row,
                                           const ull* __restrict__ kb3,
                                           ull (&acc)[4][4])
{
    ull rp[24];
    // phase A: pairs 0..13, taps j=0..10
#pragma unroll
    for (int c = 0; c < 7; ++c) {
        ulonglong2 v = *reinterpret_cast<const ulonglong2*>(row + 2 * c);
        rp[2 * c] = v.x;  rp[2 * c + 1] = v.y;
    }
#pragma unroll
    for (int j = 0; j <= 10; ++j) {
#pragma unroll
        for (int iy = 0; iy < 4; ++iy) {
            const ull kb = kb3[(3 - iy) * 21 + j];   // broadcast LDS.64
            ffma2(acc[iy][0], rp[j + 0], kb);
            ffma2(acc[iy][1], rp[j + 1], kb);
            ffma2(acc[iy][2], rp[j + 2], kb);
            ffma2(acc[iy][3], rp[j + 3], kb);
        }
    }
    asm volatile("" ::: "memory");   // keep phase-B loads from hoisting
    // phase B: pairs 14..23, taps j=11..20
#pragma unroll
    for (int c = 7; c < 12; ++c) {
        ulonglong2 v = *reinterpret_cast<const ulonglong2*>(row + 2 * c);
        rp[2 * c] = v.x;  rp[2 * c + 1] = v.y;
    }
#pragma unroll
    for (int j = 11; j <= 20; ++j) {
#pragma unroll
        for (int iy = 0; iy < 4; ++iy) {
            const ull kb = kb3[(3 - iy) * 21 + j];
            ffma2(acc[iy][0], rp[j + 0], kb);
            ffma2(acc[iy][1], rp[j + 1], kb);
            ffma2(acc[iy][2], rp[j + 2], kb);
            ffma2(acc[iy][3], rp[j + 3], kb);
        }
    }
}

// Edge row: partial iy coverage, guarded per iy (runtime rr).
__device__ __forceinline__ void edge_row(const ull* __restrict__ row,
                                         const ull* __restrict__ skd,
                                         ull (&acc)[4][4], int rr)
{
    ull rp[24];
#pragma unroll
    for (int c = 0; c < 7; ++c) {
        ulonglong2 v = *reinterpret_cast<const ulonglong2*>(row + 2 * c);
        rp[2 * c] = v.x;  rp[2 * c + 1] = v.y;
    }
#pragma unroll
    for (int iy = 0; iy < 4; ++iy) {
        const int i = rr - iy;
        if (i < 0 || i > 20) continue;
        const ull* kr = skd + i * 21;
#pragma unroll
        for (int j = 0; j <= 10; ++j) {
            const ull kb = kr[j];
            ffma2(acc[iy][0], rp[j + 0], kb);
            ffma2(acc[iy][1], rp[j + 1], kb);
            ffma2(acc[iy][2], rp[j + 2], kb);
            ffma2(acc[iy][3], rp[j + 3], kb);
        }
    }
    asm volatile("" ::: "memory");
#pragma unroll
    for (int c = 7; c < 12; ++c) {
        ulonglong2 v = *reinterpret_cast<const ulonglong2*>(row + 2 * c);
        rp[2 * c] = v.x;  rp[2 * c + 1] = v.y;
    }
#pragma unroll
    for (int iy = 0; iy < 4; ++iy) {
        const int i = rr - iy;
        if (i < 0 || i > 20) continue;
        const ull* kr = skd + i * 21;
#pragma unroll
        for (int j = 11; j <= 20; ++j) {
            const ull kb = kr[j];
            ffma2(acc[iy][0], rp[j + 0], kb);
            ffma2(acc[iy][1], rp[j + 1], kb);
            ffma2(acc[iy][2], rp[j + 2], kb);
            ffma2(acc[iy][3], rp[j + 3], kb);
        }
    }
}

__global__ void __launch_bounds__(256, 3)
blur21_kernel(const float* __restrict__ gin_all,
              const float* __restrict__ gker,
              float* __restrict__ gout_all)
{
    extern __shared__ char smem_raw[];
    ull* s_kd = reinterpret_cast<ull*>(smem_raw);                   // [441] (k,k)
    ull* s_il = reinterpret_cast<ull*>(smem_raw + SMEM_KD_BYTES);   // [84][84]

    const int tid = threadIdx.x;
    const int bc  = blockIdx.z;           // b*3 + c
    const int b   = bc / 3;

    const float* gin = gin_all + (size_t)bc * (768 * 768);
    const float* gk  = gker + b * 441;

    const int x0 = blockIdx.x * 128 - 10;
    const int y0 = blockIdx.y * 64 - 10;

    // ---- fill interleaved patch: IL[py][v] = (in[x0+v], in[x0+v+64]) ----
    {
        const int warp = tid >> 5;
        const int lane = tid & 31;
        for (int py = warp; py < IL_ROWS; py += 8) {
            const int gy = reflect768(y0 + py);
            const float* grow = gin + gy * 768;
            ull* srow = s_il + py * IL_W;
#pragma unroll
            for (int v = lane; v < IL_W; v += 32) {
                const int gx0 = reflect768(x0 + v);
                const int gx1 = reflect768(x0 + v + 64);
                srow[v] = pack2(grow[gx0], grow[gx1]);
            }
        }
    }
    // ---- kernel as pre-duplicated (k,k) pairs ----
    for (int idx = tid; idx < KD_PAIRS; idx += 256)
        s_kd[idx] = dup2(gk[idx]);
    __syncthreads();

    // thread -> outputs x in [xb,xb+4) u [xb+64,xb+68), y block of 4
    const int lx = tid & 15;    // 0..15 -> xb = lx*4 (pair columns)
    const int ly = tid >> 4;    // 0..15 -> y block of 4
    const int xb = lx * 4;

    ull acc[4][4];
#pragma unroll
    for (int iy = 0; iy < 4; ++iy)
#pragma unroll
        for (int p = 0; p < 4; ++p)
            acc[iy][p] = 0ULL;

    const ull* base = s_il + (ly * 4) * IL_W + xb;

    // prologue rows 0..2
#pragma unroll 1
    for (int rr = 0; rr < 3; ++rr)
        edge_row(base + rr * IL_W, s_kd, acc, rr);
    // steady rows 3..20
#pragma unroll 1
    for (int rr = 3; rr < 21; ++rr)
        steady_row(base + rr * IL_W, s_kd + (rr - 3) * 21, acc);
    // epilogue rows 21..23
#pragma unroll 1
    for (int rr = 21; rr < 24; ++rr)
        edge_row(base + rr * IL_W, s_kd, acc, rr);

    // ---- store: unpack pairs -> two float4 per output row ----
    float* gout = gout_all + (size_t)bc * (768 * 768)
                + (size_t)(blockIdx.y * 64 + ly * 4) * 768
                + blockIdx.x * 128 + xb;
#pragma unroll
    for (int iy = 0; iy < 4; ++iy) {
        float lo0, lo1, lo2, lo3, hi0, hi1, hi2, hi3;
        unpack2(acc[iy][0], lo0, hi0);
        unpack2(acc[iy][1], lo1, hi1);
        unpack2(acc[iy][2], lo2, hi2);
        unpack2(acc[iy][3], lo3, hi3);
        float* o = gout + iy * 768;
        *reinterpret_cast<float4*>(o)      = make_float4(lo0, lo1, lo2, lo3);
        *reinterpret_cast<float4*>(o + 64) = make_float4(hi0, hi1, hi2, hi3);
    }
}

extern "C" void kernel_launch(void* const* d_in, const int* in_sizes, int n_in,
                              void* d_out, int out_size)
{
    const float* inp = (const float*)d_in[0];   // (16,3,768,768) f32
    const float* ker = (const float*)d_in[1];   // (16,21,21) f32
    float* out = (float*)d_out;                 // (16,3,768,768) f32

    cudaFuncSetAttribute(blur21_kernel,
                         cudaFuncAttributeMaxDynamicSharedMemorySize,
                         SMEM_BYTES);

    dim3 grid(6, 12, 48);  // 768/128 x-tiles, 768/64 y-tiles, 16*3 images
    blur21_kernel<<<grid, 256, SMEM_BYTES>>>(inp, ker, out);
}